// round 2
// baseline (speedup 1.0000x reference)
#include <cuda_runtime.h>
#include <math.h>

// Problem dims (fixed by the reference):
//   decoder_output [B=64, T=128, O=1024]  fp32
//   encoder_outputs [B=64, S=1024, I=1024] fp32
//   encoder_padding_mask [B, S] bool -> passed as int32
//   W_attn [I=1024, O=1024], W_out [O=1024, I+O=2048], b_out [1024]
// Outputs: attn_outputs [B,T,O] then attn_weights [B,T,S] concatenated in d_out.

#define BM 64
#define BN 64
#define BK 16

// Scratch (allocation-free rule: use __device__ globals)
__device__ float g_qproj[8192 * 1024];  // [B*T, I]
__device__ float g_ctx[8192 * 1024];    // [B*T, I]

// ---------------------------------------------------------------------------
// Generic NT SGEMM: C[M,N] = A[M,K] * B[N,K]^T, row-major, batched via z.
// ---------------------------------------------------------------------------
__global__ void __launch_bounds__(256) sgemm_nt(
    const float* __restrict__ A, const float* __restrict__ B, float* __restrict__ C,
    int M, int N, int K, long long sA, long long sB, long long sC)
{
    A += (long long)blockIdx.z * sA;
    B += (long long)blockIdx.z * sB;
    C += (long long)blockIdx.z * sC;

    __shared__ __align__(16) float As[BK][BM + 4];
    __shared__ __align__(16) float Bs[BK][BN + 4];

    const int tid = threadIdx.x;
    const int tx = tid & 15, ty = tid >> 4;
    const int m0 = blockIdx.y * BM, n0 = blockIdx.x * BN;

    const int lr = tid >> 2;        // 0..63 (tile row)
    const int lc = (tid & 3) * 4;   // 0,4,8,12 (k offset)

    float acc[4][4] = {};

    for (int k0 = 0; k0 < K; k0 += BK) {
        float4 a4 = *reinterpret_cast<const float4*>(A + (long long)(m0 + lr) * K + k0 + lc);
        float4 b4 = *reinterpret_cast<const float4*>(B + (long long)(n0 + lr) * K + k0 + lc);
        As[lc + 0][lr] = a4.x; As[lc + 1][lr] = a4.y; As[lc + 2][lr] = a4.z; As[lc + 3][lr] = a4.w;
        Bs[lc + 0][lr] = b4.x; Bs[lc + 1][lr] = b4.y; Bs[lc + 2][lr] = b4.z; Bs[lc + 3][lr] = b4.w;
        __syncthreads();
        #pragma unroll
        for (int kk = 0; kk < BK; kk++) {
            float4 av = *reinterpret_cast<const float4*>(&As[kk][ty * 4]);
            float4 bv = *reinterpret_cast<const float4*>(&Bs[kk][tx * 4]);
            float am[4] = {av.x, av.y, av.z, av.w};
            float bm[4] = {bv.x, bv.y, bv.z, bv.w};
            #pragma unroll
            for (int i = 0; i < 4; i++)
                #pragma unroll
                for (int j = 0; j < 4; j++)
                    acc[i][j] = fmaf(am[i], bm[j], acc[i][j]);
        }
        __syncthreads();
    }

    #pragma unroll
    for (int i = 0; i < 4; i++) {
        float4 o = {acc[i][0], acc[i][1], acc[i][2], acc[i][3]};
        *reinterpret_cast<float4*>(C + (long long)(m0 + ty * 4 + i) * N + n0 + tx * 4) = o;
    }
}

// ---------------------------------------------------------------------------
// Generic NN SGEMM: C[M,N] = A[M,K] * B[K,N], row-major, batched via z.
// ---------------------------------------------------------------------------
__global__ void __launch_bounds__(256) sgemm_nn(
    const float* __restrict__ A, const float* __restrict__ B, float* __restrict__ C,
    int M, int N, int K, long long sA, long long sB, long long sC)
{
    A += (long long)blockIdx.z * sA;
    B += (long long)blockIdx.z * sB;
    C += (long long)blockIdx.z * sC;

    __shared__ __align__(16) float As[BK][BM + 4];
    __shared__ __align__(16) float Bs[BK][BN + 4];

    const int tid = threadIdx.x;
    const int tx = tid & 15, ty = tid >> 4;
    const int m0 = blockIdx.y * BM, n0 = blockIdx.x * BN;

    const int lr = tid >> 2;        // A tile row 0..63
    const int lc = (tid & 3) * 4;   // A k offset

    const int br = tid >> 4;        // B tile k-row 0..15
    const int bc = (tid & 15) * 4;  // B tile n-col 0..60

    float acc[4][4] = {};

    for (int k0 = 0; k0 < K; k0 += BK) {
        float4 a4 = *reinterpret_cast<const float4*>(A + (long long)(m0 + lr) * K + k0 + lc);
        float4 b4 = *reinterpret_cast<const float4*>(B + (long long)(k0 + br) * N + n0 + bc);
        As[lc + 0][lr] = a4.x; As[lc + 1][lr] = a4.y; As[lc + 2][lr] = a4.z; As[lc + 3][lr] = a4.w;
        Bs[br][bc + 0] = b4.x; Bs[br][bc + 1] = b4.y; Bs[br][bc + 2] = b4.z; Bs[br][bc + 3] = b4.w;
        __syncthreads();
        #pragma unroll
        for (int kk = 0; kk < BK; kk++) {
            float4 av = *reinterpret_cast<const float4*>(&As[kk][ty * 4]);
            float4 bv = *reinterpret_cast<const float4*>(&Bs[kk][tx * 4]);
            float am[4] = {av.x, av.y, av.z, av.w};
            float bm[4] = {bv.x, bv.y, bv.z, bv.w};
            #pragma unroll
            for (int i = 0; i < 4; i++)
                #pragma unroll
                for (int j = 0; j < 4; j++)
                    acc[i][j] = fmaf(am[i], bm[j], acc[i][j]);
        }
        __syncthreads();
    }

    #pragma unroll
    for (int i = 0; i < 4; i++) {
        float4 o = {acc[i][0], acc[i][1], acc[i][2], acc[i][3]};
        *reinterpret_cast<float4*>(C + (long long)(m0 + ty * 4 + i) * N + n0 + tx * 4) = o;
    }
}

// ---------------------------------------------------------------------------
// Output GEMM with virtual concat A = [A0 | A1] (each [M,KH]), NT vs B[N,2*KH],
// epilogue tanh(acc + bias[n]).
// ---------------------------------------------------------------------------
__global__ void __launch_bounds__(256) sgemm_cat_tanh(
    const float* __restrict__ A0, const float* __restrict__ A1,
    const float* __restrict__ B, const float* __restrict__ bias,
    float* __restrict__ C, int M, int N, int KH)
{
    __shared__ __align__(16) float As[BK][BM + 4];
    __shared__ __align__(16) float Bs[BK][BN + 4];

    const int tid = threadIdx.x;
    const int tx = tid & 15, ty = tid >> 4;
    const int m0 = blockIdx.y * BM, n0 = blockIdx.x * BN;

    const int lr = tid >> 2;
    const int lc = (tid & 3) * 4;
    const int K = 2 * KH;

    float acc[4][4] = {};

    for (int k0 = 0; k0 < K; k0 += BK) {
        int kg = k0 + lc;
        const float* aptr = (kg < KH)
            ? (A0 + (long long)(m0 + lr) * KH + kg)
            : (A1 + (long long)(m0 + lr) * KH + (kg - KH));
        float4 a4 = *reinterpret_cast<const float4*>(aptr);
        float4 b4 = *reinterpret_cast<const float4*>(B + (long long)(n0 + lr) * K + k0 + lc);
        As[lc + 0][lr] = a4.x; As[lc + 1][lr] = a4.y; As[lc + 2][lr] = a4.z; As[lc + 3][lr] = a4.w;
        Bs[lc + 0][lr] = b4.x; Bs[lc + 1][lr] = b4.y; Bs[lc + 2][lr] = b4.z; Bs[lc + 3][lr] = b4.w;
        __syncthreads();
        #pragma unroll
        for (int kk = 0; kk < BK; kk++) {
            float4 av = *reinterpret_cast<const float4*>(&As[kk][ty * 4]);
            float4 bv = *reinterpret_cast<const float4*>(&Bs[kk][tx * 4]);
            float am[4] = {av.x, av.y, av.z, av.w};
            float bm[4] = {bv.x, bv.y, bv.z, bv.w};
            #pragma unroll
            for (int i = 0; i < 4; i++)
                #pragma unroll
                for (int j = 0; j < 4; j++)
                    acc[i][j] = fmaf(am[i], bm[j], acc[i][j]);
        }
        __syncthreads();
    }

    #pragma unroll
    for (int i = 0; i < 4; i++) {
        float4 o;
        o.x = tanhf(acc[i][0] + bias[n0 + tx * 4 + 0]);
        o.y = tanhf(acc[i][1] + bias[n0 + tx * 4 + 1]);
        o.z = tanhf(acc[i][2] + bias[n0 + tx * 4 + 2]);
        o.w = tanhf(acc[i][3] + bias[n0 + tx * 4 + 3]);
        *reinterpret_cast<float4*>(C + (long long)(m0 + ty * 4 + i) * N + n0 + tx * 4) = o;
    }
}

// ---------------------------------------------------------------------------
// Masked softmax over rows of [B*T, S=1024], in place.
// mask is int32 (bool promoted): mask[b][s] != 0 -> weight 0.
// ---------------------------------------------------------------------------
__device__ __forceinline__ float warpMax(float v) {
    #pragma unroll
    for (int o = 16; o; o >>= 1) v = fmaxf(v, __shfl_xor_sync(0xffffffffu, v, o));
    return v;
}
__device__ __forceinline__ float warpSum(float v) {
    #pragma unroll
    for (int o = 16; o; o >>= 1) v += __shfl_xor_sync(0xffffffffu, v, o);
    return v;
}

__global__ void __launch_bounds__(256) softmax_mask(
    float* __restrict__ w, const int* __restrict__ mask, int T)
{
    const int S = 1024;
    long long row = blockIdx.x;
    int b = (int)(row / T);
    float* sr = w + row * S;
    const int* mr = mask + (long long)b * S;
    int tid = threadIdx.x;

    float4 v = *reinterpret_cast<const float4*>(sr + tid * 4);
    int4 m = *reinterpret_cast<const int4*>(mr + tid * 4);

    float x[4];
    bool msk[4] = {m.x != 0, m.y != 0, m.z != 0, m.w != 0};
    x[0] = msk[0] ? -INFINITY : v.x;
    x[1] = msk[1] ? -INFINITY : v.y;
    x[2] = msk[2] ? -INFINITY : v.z;
    x[3] = msk[3] ? -INFINITY : v.w;

    float mx = fmaxf(fmaxf(x[0], x[1]), fmaxf(x[2], x[3]));

    __shared__ float sh[8];
    float wm = warpMax(mx);
    if ((tid & 31) == 0) sh[tid >> 5] = wm;
    __syncthreads();
    if (tid < 32) {
        float t = (tid < 8) ? sh[tid] : -INFINITY;
        t = warpMax(t);
        if (tid == 0) sh[0] = t;
    }
    __syncthreads();
    mx = sh[0];

    float e[4], s = 0.f;
    #pragma unroll
    for (int j = 0; j < 4; j++) {
        e[j] = msk[j] ? 0.f : __expf(x[j] - mx);
        s += e[j];
    }
    __syncthreads();  // protect sh reuse
    float ws = warpSum(s);
    if ((tid & 31) == 0) sh[tid >> 5] = ws;
    __syncthreads();
    if (tid < 32) {
        float t = (tid < 8) ? sh[tid] : 0.f;
        t = warpSum(t);
        if (tid == 0) sh[0] = t;
    }
    __syncthreads();
    float inv = 1.0f / sh[0];

    float4 o = {e[0] * inv, e[1] * inv, e[2] * inv, e[3] * inv};
    *reinterpret_cast<float4*>(sr + tid * 4) = o;
}

// ---------------------------------------------------------------------------
extern "C" void kernel_launch(void* const* d_in, const int* in_sizes, int n_in,
                              void* d_out, int out_size)
{
    const float* dec    = (const float*)d_in[0];          // [64,128,1024]
    const float* enc    = (const float*)d_in[1];          // [64,1024,1024]
    const int*   mask   = (const int*)d_in[2];            // [64,1024] bool->int32
    const float* W_attn = (const float*)d_in[3];          // [1024,1024]
    const float* W_out  = (const float*)d_in[4];          // [1024,2048]
    const float* b_out  = (const float*)d_in[5];          // [1024]

    float* out     = (float*)d_out;                       // attn_outputs [64,128,1024]
    float* weights = out + (long long)8192 * 1024;        // attn_weights [64,128,1024]

    float* qp = nullptr;
    float* cp = nullptr;
    cudaGetSymbolAddress((void**)&qp, g_qproj);
    cudaGetSymbolAddress((void**)&cp, g_ctx);

    const int B = 64, T = 128, S = 1024, I = 1024, O = 1024;
    const int M = B * T;  // 8192

    // 1) q_proj[m,i] = sum_o dec[m,o] * W_attn[i,o]   (NT, M=8192,N=1024,K=1024)
    sgemm_nt<<<dim3(I / BN, M / BM, 1), 256>>>(dec, W_attn, qp, M, I, O, 0, 0, 0);

    // 2) scores[b][t,s] = sum_i q[b][t,i] * enc[b][s,i]  (batched NT)
    sgemm_nt<<<dim3(S / BN, T / BM, B), 256>>>(
        qp, enc, weights, T, S, I,
        (long long)T * I, (long long)S * I, (long long)T * S);

    // 3) masked softmax over rows, in place in the weights output region
    softmax_mask<<<M, 256>>>(weights, mask, T);

    // 4) context[b][t,i] = sum_s w[b][t,s] * enc[b][s,i]  (batched NN)
    sgemm_nn<<<dim3(I / BN, T / BM, B), 256>>>(
        weights, enc, cp, T, I, S,
        (long long)T * S, (long long)S * I, (long long)T * I);

    // 5) out[m,o] = tanh(sum_c [ctx|dec][m,c] * W_out[o,c] + b[o])  (NT, K=2048)
    sgemm_cat_tanh<<<dim3(O / BN, M / BM, 1), 256>>>(cp, dec, W_out, b_out, out, M, O, I);
}

// round 5
// speedup vs baseline: 1.5673x; 1.5673x over previous
#include <cuda_runtime.h>
#include <cuda_bf16.h>
#include <math.h>
#include <stdint.h>

// ============================================================================
// Problem dims
// ============================================================================
#define B_ 64
#define T_ 128
#define S_ 1024
#define I_ 1024
#define O_ 1024
#define M_ (B_*T_)   // 8192
#define C_ (I_+O_)   // 2048

// ============================================================================
// Scratch (__device__ globals; allocation-free rule)
// ============================================================================
__device__ __nv_bfloat16 g_dec3[M_ * 3 * O_];                 // [8192, 3072] (h|m|l)
__device__ __nv_bfloat16 g_wa3[I_ * 3 * O_];                  // [1024, 3072]
__device__ __nv_bfloat16 g_qp2[M_ * 2 * I_];                  // [8192, 2048] (h|l)
__device__ __nv_bfloat16 g_enc2[(size_t)B_ * S_ * 2 * I_];    // [64][1024, 2048]
__device__ __nv_bfloat16 g_encT2[(size_t)B_ * I_ * 2 * S_];   // [64][1024, 2048] transposed
__device__ __nv_bfloat16 g_w2[M_ * 2 * S_];                   // [8192, 2048]
__device__ __nv_bfloat16 g_cat2[(size_t)M_ * 2 * C_];         // [8192, 4096] ([ctx|dec] h then l)
__device__ __nv_bfloat16 g_wo2[O_ * 2 * C_];                  // [1024, 4096]

// ============================================================================
// Helpers
// ============================================================================
__device__ __forceinline__ uint32_t smem_u32(const void* p) {
    uint32_t a;
    asm("{ .reg .u64 t; cvta.to.shared.u64 t, %1; cvt.u32.u64 %0, t; }" : "=r"(a) : "l"(p));
    return a;
}

__device__ __forceinline__ void ldsm4(uint32_t r[4], uint32_t addr) {
    asm volatile("ldmatrix.sync.aligned.m8n8.x4.shared.b16 {%0,%1,%2,%3}, [%4];"
        : "=r"(r[0]), "=r"(r[1]), "=r"(r[2]), "=r"(r[3]) : "r"(addr));
}

__device__ __forceinline__ void mma_bf16(float d[4], const uint32_t a[4], const uint32_t b[2]) {
    asm volatile(
        "mma.sync.aligned.m16n8k16.row.col.f32.bf16.bf16.f32 "
        "{%0,%1,%2,%3}, {%4,%5,%6,%7}, {%8,%9}, {%0,%1,%2,%3};"
        : "+f"(d[0]), "+f"(d[1]), "+f"(d[2]), "+f"(d[3])
        : "r"(a[0]), "r"(a[1]), "r"(a[2]), "r"(a[3]), "r"(b[0]), "r"(b[1]));
}

__device__ __forceinline__ void split2f(float x, __nv_bfloat16& h, __nv_bfloat16& l) {
    h = __float2bfloat16(x);
    l = __float2bfloat16(x - __bfloat162float(h));
}

// ============================================================================
// HMMA tensor GEMM. NT, K-major both operands stored as [rows, NSLAB*K],
// slab s at column offset s*K. D = sum over pairs (PA[p],PB[p]) of Aslab*Bslab^T.
// CTA tile 128x128, chunk BK=64. 8 warps: 2(m) x 4(n), each 64x32.
// EPI: 0 = fp32 store, 1 = tanh(acc+bias) fp32 store, 2 = split2 bf16 store
// ============================================================================
#define TILEB 16384  // bytes of one 128x64 bf16 SW128 tile

template<int NSLAB, int NPAIR, int EPI>
__global__ void __launch_bounds__(256) tgemm(
    const __nv_bfloat16* __restrict__ A, const __nv_bfloat16* __restrict__ B,
    float* __restrict__ Cf, __nv_bfloat16* __restrict__ Cs,
    const float* __restrict__ bias,
    int K, long long sA, long long sB, long long sC,
    int ldc, int splitOff)
{
    extern __shared__ char smem[];
    const uint32_t sb = smem_u32(smem);
    const int tid = threadIdx.x;
    const int lane = tid & 31, wid = tid >> 5;
    const int wm = wid & 1, wn = wid >> 1;         // warp tile: (wm*64, wn*32)
    const int n0 = blockIdx.x * 128, m0 = blockIdx.y * 128;
    const long long z = blockIdx.z;

    const __nv_bfloat16* Ab = A + z * sA;
    const __nv_bfloat16* Bb = B + z * sB;

    const int PA[6] = {0, 0, 1, 0, 2, 1};
    const int PB[6] = {0, 1, 0, 2, 0, 1};

    const int rowlen = NSLAB * K;
    const int nchunk = K >> 6;

    float acc[4][4][4];
    #pragma unroll
    for (int i = 0; i < 4; i++)
        #pragma unroll
        for (int j = 0; j < 4; j++)
            #pragma unroll
            for (int q = 0; q < 4; q++) acc[i][j][q] = 0.f;

    // ldmatrix lane-address components
    const int g = lane >> 3, lr = lane & 7;
    const int a_r  = lr + (g & 1) * 8;   // A: row add
    const int a_kb = (g >> 1) * 16;      // A: k-byte add
    const int b_r  = lr + (g >> 1) * 8;  // B: row add
    const int b_kb = (g & 1) * 16;       // B: k-byte add

    for (int c = 0; c < nchunk; c++) {
        const int k0 = c << 6;
        // ---- load NSLAB A-tiles + NSLAB B-tiles (128x64 bf16, SW128) ----
        #pragma unroll
        for (int s = 0; s < NSLAB; s++) {
            #pragma unroll
            for (int j = 0; j < 4; j++) {
                int v = tid + 256 * j;
                int r = v >> 3, cc = (v & 7) << 3;
                uint4 d = *reinterpret_cast<const uint4*>(Ab + (long long)(m0 + r) * rowlen + s * K + k0 + cc);
                uint32_t off = (uint32_t)(r * 128 + cc * 2);
                off ^= (off >> 3) & 0x70u;
                *reinterpret_cast<uint4*>(smem + s * TILEB + off) = d;
            }
            #pragma unroll
            for (int j = 0; j < 4; j++) {
                int v = tid + 256 * j;
                int r = v >> 3, cc = (v & 7) << 3;
                uint4 d = *reinterpret_cast<const uint4*>(Bb + (long long)(n0 + r) * rowlen + s * K + k0 + cc);
                uint32_t off = (uint32_t)(r * 128 + cc * 2);
                off ^= (off >> 3) & 0x70u;
                *reinterpret_cast<uint4*>(smem + (NSLAB + s) * TILEB + off) = d;
            }
        }
        __syncthreads();

        // ---- compute: NPAIR slab-pairs over this 64-wide K chunk ----
        #pragma unroll
        for (int p = 0; p < NPAIR; p++) {
            const uint32_t aBase = sb + PA[p] * TILEB;
            const uint32_t bBase = sb + (NSLAB + PB[p]) * TILEB;
            #pragma unroll
            for (int kt = 0; kt < 4; kt++) {       // 4 k16 steps
                uint32_t afr[4][4], bfr[2][4];
                #pragma unroll
                for (int mt = 0; mt < 4; mt++) {
                    uint32_t off = (uint32_t)((wm * 64 + mt * 16 + a_r) * 128 + kt * 32 + a_kb);
                    off ^= (off >> 3) & 0x70u;
                    ldsm4(afr[mt], aBase + off);
                }
                #pragma unroll
                for (int ntp = 0; ntp < 2; ntp++) {
                    uint32_t off = (uint32_t)((wn * 32 + ntp * 16 + b_r) * 128 + kt * 32 + b_kb);
                    off ^= (off >> 3) & 0x70u;
                    ldsm4(bfr[ntp], bBase + off);
                }
                #pragma unroll
                for (int mt = 0; mt < 4; mt++)
                    #pragma unroll
                    for (int nt = 0; nt < 4; nt++)
                        mma_bf16(acc[mt][nt], afr[mt], &bfr[nt >> 1][(nt & 1) * 2]);
            }
        }
        __syncthreads();
    }

    // ---- epilogue (register accumulators) ----
    const int qr = lane >> 2;          // row within 8
    const int qc = (lane & 3) * 2;     // col pair
    #pragma unroll
    for (int mt = 0; mt < 4; mt++) {
        #pragma unroll
        for (int nt = 0; nt < 4; nt++) {
            const long long row0 = m0 + wm * 64 + mt * 16 + qr;
            const long long row1 = row0 + 8;
            const int col = n0 + wn * 32 + nt * 8 + qc;
            float v00 = acc[mt][nt][0], v01 = acc[mt][nt][1];
            float v10 = acc[mt][nt][2], v11 = acc[mt][nt][3];
            if (EPI == 0) {
                *reinterpret_cast<float2*>(Cf + z * sC + row0 * ldc + col) = make_float2(v00, v01);
                *reinterpret_cast<float2*>(Cf + z * sC + row1 * ldc + col) = make_float2(v10, v11);
            } else if (EPI == 1) {
                float b0 = bias[col], b1 = bias[col + 1];
                *reinterpret_cast<float2*>(Cf + z * sC + row0 * ldc + col) =
                    make_float2(tanhf(v00 + b0), tanhf(v01 + b1));
                *reinterpret_cast<float2*>(Cf + z * sC + row1 * ldc + col) =
                    make_float2(tanhf(v10 + b0), tanhf(v11 + b1));
            } else {
                __nv_bfloat16 h0, l0, h1, l1;
                split2f(v00, h0, l0); split2f(v01, h1, l1);
                *reinterpret_cast<__nv_bfloat162*>(Cs + z * sC + row0 * ldc + col) =
                    __nv_bfloat162(h0, h1);
                *reinterpret_cast<__nv_bfloat162*>(Cs + z * sC + row0 * ldc + splitOff + col) =
                    __nv_bfloat162(l0, l1);
                split2f(v10, h0, l0); split2f(v11, h1, l1);
                *reinterpret_cast<__nv_bfloat162*>(Cs + z * sC + row1 * ldc + col) =
                    __nv_bfloat162(h0, h1);
                *reinterpret_cast<__nv_bfloat162*>(Cs + z * sC + row1 * ldc + splitOff + col) =
                    __nv_bfloat162(l0, l1);
            }
        }
    }
}

// ============================================================================
// Conversion kernels
// ============================================================================
__global__ void __launch_bounds__(256) split3_kernel(
    const float* __restrict__ src, __nv_bfloat16* __restrict__ dst, int K)
{
    long long i = (long long)blockIdx.x * blockDim.x + threadIdx.x;
    long long rr = i / K;
    int k = (int)(i - rr * K);
    float x = src[i];
    __nv_bfloat16 h = __float2bfloat16(x);
    float rm = x - __bfloat162float(h);
    __nv_bfloat16 m = __float2bfloat16(rm);
    __nv_bfloat16 l = __float2bfloat16(rm - __bfloat162float(m));
    __nv_bfloat16* row = dst + rr * (3LL * K);
    row[k] = h; row[K + k] = m; row[2 * K + k] = l;
}

__global__ void __launch_bounds__(256) split2_kernel(
    const float* __restrict__ src, __nv_bfloat16* __restrict__ dst, int K)
{
    long long i = (long long)blockIdx.x * blockDim.x + threadIdx.x;
    long long rr = i / K;
    int k = (int)(i - rr * K);
    __nv_bfloat16 h, l;
    split2f(src[i], h, l);
    __nv_bfloat16* row = dst + rr * (2LL * K);
    row[k] = h; row[K + k] = l;
}

// dec -> cat region: cat [8192, 4096]: hi slab cols [0,2048), lo [2048,4096);
// dec occupies cat cols [1024,2048) -> hi at 1024+o, lo at 3072+o
__global__ void __launch_bounds__(256) dec_to_cat_kernel(
    const float* __restrict__ dec, __nv_bfloat16* __restrict__ cat)
{
    long long i = (long long)blockIdx.x * blockDim.x + threadIdx.x;  // over 8192*1024
    long long m = i >> 10;
    int o = (int)(i & 1023);
    __nv_bfloat16 h, l;
    split2f(dec[i], h, l);
    cat[m * 4096 + 1024 + o] = h;
    cat[m * 4096 + 3072 + o] = l;
}

// enc -> enc2 [b][s, 2048] and encT2 [b][i, 2048] (transposed), both h|l
__global__ void __launch_bounds__(1024) enc_split_kernel(
    const float* __restrict__ enc, __nv_bfloat16* __restrict__ e2, __nv_bfloat16* __restrict__ eT2)
{
    __shared__ __nv_bfloat16 sh[32][33], sl[32][33];
    int b = blockIdx.z;
    int i0 = blockIdx.x * 32, s0 = blockIdx.y * 32;
    int tx = threadIdx.x, ty = threadIdx.y;
    const float* eb = enc + (size_t)b * S_ * I_;
    float x = eb[(size_t)(s0 + ty) * I_ + i0 + tx];
    __nv_bfloat16 h, l;
    split2f(x, h, l);
    __nv_bfloat16* e2b = e2 + (size_t)b * S_ * 2 * I_;
    e2b[(size_t)(s0 + ty) * 2048 + i0 + tx] = h;
    e2b[(size_t)(s0 + ty) * 2048 + 1024 + i0 + tx] = l;
    sh[ty][tx] = h; sl[ty][tx] = l;
    __syncthreads();
    __nv_bfloat16* eTb = eT2 + (size_t)b * I_ * 2 * S_;
    eTb[(size_t)(i0 + ty) * 2048 + s0 + tx] = sh[tx][ty];
    eTb[(size_t)(i0 + ty) * 2048 + 1024 + s0 + tx] = sl[tx][ty];
}

// ============================================================================
// Masked softmax over rows of [B*T, S=1024], in place (fp32), + fused 2-way
// split to wsplit [row, 2048]. mask int32: !=0 -> weight 0.
// ============================================================================
__device__ __forceinline__ float warpMax(float v) {
    #pragma unroll
    for (int o = 16; o; o >>= 1) v = fmaxf(v, __shfl_xor_sync(0xffffffffu, v, o));
    return v;
}
__device__ __forceinline__ float warpSum(float v) {
    #pragma unroll
    for (int o = 16; o; o >>= 1) v += __shfl_xor_sync(0xffffffffu, v, o);
    return v;
}

__global__ void __launch_bounds__(256) softmax_mask(
    float* __restrict__ w, const int* __restrict__ mask, __nv_bfloat16* __restrict__ wsplit)
{
    const int S = 1024;
    long long row = blockIdx.x;
    int b = (int)(row >> 7);  // T = 128
    float* sr = w + row * S;
    const int* mr = mask + (long long)b * S;
    int tid = threadIdx.x;

    float4 v = *reinterpret_cast<const float4*>(sr + tid * 4);
    int4 m = *reinterpret_cast<const int4*>(mr + tid * 4);

    bool msk[4] = {m.x != 0, m.y != 0, m.z != 0, m.w != 0};
    float x[4];
    x[0] = msk[0] ? -INFINITY : v.x;
    x[1] = msk[1] ? -INFINITY : v.y;
    x[2] = msk[2] ? -INFINITY : v.z;
    x[3] = msk[3] ? -INFINITY : v.w;

    float mx = fmaxf(fmaxf(x[0], x[1]), fmaxf(x[2], x[3]));

    __shared__ float sh[8];
    float wm = warpMax(mx);
    if ((tid & 31) == 0) sh[tid >> 5] = wm;
    __syncthreads();
    if (tid < 32) {
        float t = (tid < 8) ? sh[tid] : -INFINITY;
        t = warpMax(t);
        if (tid == 0) sh[0] = t;
    }
    __syncthreads();
    mx = sh[0];

    float e[4], s = 0.f;
    #pragma unroll
    for (int j = 0; j < 4; j++) {
        e[j] = msk[j] ? 0.f : __expf(x[j] - mx);
        s += e[j];
    }
    __syncthreads();
    float ws = warpSum(s);
    if ((tid & 31) == 0) sh[tid >> 5] = ws;
    __syncthreads();
    if (tid < 32) {
        float t = (tid < 8) ? sh[tid] : 0.f;
        t = warpSum(t);
        if (tid == 0) sh[0] = t;
    }
    __syncthreads();
    float inv = 1.0f / sh[0];

    float o[4] = {e[0] * inv, e[1] * inv, e[2] * inv, e[3] * inv};
    float4 of = {o[0], o[1], o[2], o[3]};
    *reinterpret_cast<float4*>(sr + tid * 4) = of;

    __nv_bfloat16* wrow = wsplit + row * 2048;
    #pragma unroll
    for (int j = 0; j < 4; j++) {
        __nv_bfloat16 h, l;
        split2f(o[j], h, l);
        wrow[tid * 4 + j] = h;
        wrow[1024 + tid * 4 + j] = l;
    }
}

// ============================================================================
extern "C" void kernel_launch(void* const* d_in, const int* in_sizes, int n_in,
                              void* d_out, int out_size)
{
    const float* dec    = (const float*)d_in[0];   // [64,128,1024]
    const float* enc    = (const float*)d_in[1];   // [64,1024,1024]
    const int*   mask   = (const int*)d_in[2];     // [64,1024] bool->int32
    const float* W_attn = (const float*)d_in[3];   // [1024,1024]
    const float* W_out  = (const float*)d_in[4];   // [1024,2048]
    const float* b_out  = (const float*)d_in[5];   // [1024]

    float* out     = (float*)d_out;                 // attn_outputs [64,128,1024]
    float* weights = out + (long long)M_ * O_;      // attn_weights [64,128,1024]

    __nv_bfloat16 *dec3, *wa3, *qp2, *enc2, *encT2, *w2, *cat2, *wo2;
    cudaGetSymbolAddress((void**)&dec3,  g_dec3);
    cudaGetSymbolAddress((void**)&wa3,   g_wa3);
    cudaGetSymbolAddress((void**)&qp2,   g_qp2);
    cudaGetSymbolAddress((void**)&enc2,  g_enc2);
    cudaGetSymbolAddress((void**)&encT2, g_encT2);
    cudaGetSymbolAddress((void**)&w2,    g_w2);
    cudaGetSymbolAddress((void**)&cat2,  g_cat2);
    cudaGetSymbolAddress((void**)&wo2,   g_wo2);

    const int SM3 = 6 * TILEB;  // 98304
    const int SM2 = 4 * TILEB;  // 65536
    cudaFuncSetAttribute((const void*)tgemm<3, 6, 2>, cudaFuncAttributeMaxDynamicSharedMemorySize, SM3);
    cudaFuncSetAttribute((const void*)tgemm<2, 3, 0>, cudaFuncAttributeMaxDynamicSharedMemorySize, SM2);
    cudaFuncSetAttribute((const void*)tgemm<2, 3, 2>, cudaFuncAttributeMaxDynamicSharedMemorySize, SM2);
    cudaFuncSetAttribute((const void*)tgemm<2, 3, 1>, cudaFuncAttributeMaxDynamicSharedMemorySize, SM2);

    // --- Conversions ---
    split3_kernel<<<(M_ * (long long)O_) / 256, 256>>>(dec, dec3, O_);
    split3_kernel<<<(I_ * (long long)O_) / 256, 256>>>(W_attn, wa3, O_);
    enc_split_kernel<<<dim3(I_ / 32, S_ / 32, B_), dim3(32, 32)>>>(enc, enc2, encT2);
    split2_kernel<<<(O_ * (long long)C_) / 256, 256>>>(W_out, wo2, C_);
    dec_to_cat_kernel<<<(M_ * (long long)O_) / 256, 256>>>(dec, cat2);

    // --- GEMM1: q_proj = dec . W_attn^T  (3-way split, 6 passes) -> qp2 split ---
    tgemm<3, 6, 2><<<dim3(I_ / 128, M_ / 128, 1), 256, SM3>>>(
        dec3, wa3, nullptr, qp2, nullptr,
        O_, 0, 0, 0, 2 * I_, I_);

    // --- GEMM2: scores[b] = q[b] . enc[b]^T  (2-way split) -> weights fp32 ---
    tgemm<2, 3, 0><<<dim3(S_ / 128, T_ / 128, B_), 256, SM2>>>(
        qp2, enc2, weights, nullptr, nullptr,
        I_, (long long)T_ * 2 * I_, (long long)S_ * 2 * I_, (long long)T_ * S_,
        S_, 0);

    // --- Softmax + fused split -> w2 ---
    softmax_mask<<<M_, 256>>>(weights, mask, w2);

    // --- GEMM4: ctx[b] = w[b] . encT[b]^T -> cat2 split (ctx cols [0,1024)) ---
    tgemm<2, 3, 2><<<dim3(I_ / 128, T_ / 128, B_), 256, SM2>>>(
        w2, encT2, nullptr, cat2, nullptr,
        S_, (long long)T_ * 2 * S_, (long long)I_ * 2 * S_, (long long)T_ * 2 * C_,
        2 * C_, C_);

    // --- GEMM5: out = tanh(cat . W_out^T + b) ---
    tgemm<2, 3, 1><<<dim3(O_ / 128, M_ / 128, 1), 256, SM2>>>(
        cat2, wo2, out, nullptr, b_out,
        C_, 0, 0, 0, O_, 0);
}

// round 6
// speedup vs baseline: 1.9058x; 1.2159x over previous
#include <cuda_runtime.h>
#include <cuda_bf16.h>
#include <math.h>
#include <stdint.h>

// ============================================================================
// Problem dims
// ============================================================================
#define B_ 64
#define T_ 128
#define S_ 1024
#define I_ 1024
#define O_ 1024
#define M_ (B_*T_)   // 8192
#define C_ (I_+O_)   // 2048

// ============================================================================
// Scratch (__device__ globals; allocation-free rule)
// ============================================================================
__device__ __nv_bfloat16 g_dec3[M_ * 3 * O_];                 // [8192, 3072] (h|m|l)
__device__ __nv_bfloat16 g_wa3[I_ * 3 * O_];                  // [1024, 3072]
__device__ __nv_bfloat16 g_qp2[M_ * 2 * I_];                  // [8192, 2048] (h|l)
__device__ __nv_bfloat16 g_enc2[(size_t)B_ * S_ * 2 * I_];    // [64][1024, 2048]
__device__ __nv_bfloat16 g_encT2[(size_t)B_ * I_ * 2 * S_];   // [64][1024, 2048] transposed
__device__ __nv_bfloat16 g_w2[M_ * 2 * S_];                   // [8192, 2048]
__device__ __nv_bfloat16 g_cat2[(size_t)M_ * 2 * C_];         // [8192, 4096] ([ctx|dec] h then l)
__device__ __nv_bfloat16 g_wo2[O_ * 2 * C_];                  // [1024, 4096]

// ============================================================================
// Helpers
// ============================================================================
__device__ __forceinline__ uint32_t smem_u32(const void* p) {
    uint32_t a;
    asm("{ .reg .u64 t; cvta.to.shared.u64 t, %1; cvt.u32.u64 %0, t; }" : "=r"(a) : "l"(p));
    return a;
}

__device__ __forceinline__ void ldsm4(uint32_t r[4], uint32_t addr) {
    asm volatile("ldmatrix.sync.aligned.m8n8.x4.shared.b16 {%0,%1,%2,%3}, [%4];"
        : "=r"(r[0]), "=r"(r[1]), "=r"(r[2]), "=r"(r[3]) : "r"(addr));
}

__device__ __forceinline__ void mma_bf16(float d[4], const uint32_t a[4], const uint32_t b[2]) {
    asm volatile(
        "mma.sync.aligned.m16n8k16.row.col.f32.bf16.bf16.f32 "
        "{%0,%1,%2,%3}, {%4,%5,%6,%7}, {%8,%9}, {%0,%1,%2,%3};"
        : "+f"(d[0]), "+f"(d[1]), "+f"(d[2]), "+f"(d[3])
        : "r"(a[0]), "r"(a[1]), "r"(a[2]), "r"(a[3]), "r"(b[0]), "r"(b[1]));
}

__device__ __forceinline__ void split2f(float x, __nv_bfloat16& h, __nv_bfloat16& l) {
    h = __float2bfloat16(x);
    l = __float2bfloat16(x - __bfloat162float(h));
}

#define CP_ASYNC16(dst, src) \
    asm volatile("cp.async.cg.shared.global [%0], [%1], 16;" :: "r"(dst), "l"(src))
#define CP_COMMIT() asm volatile("cp.async.commit_group;" ::: "memory")
#define CP_WAIT1()  asm volatile("cp.async.wait_group 1;" ::: "memory")
#define CP_WAIT0()  asm volatile("cp.async.wait_group 0;" ::: "memory")

// ============================================================================
// HMMA tensor GEMM with 2-stage cp.async pipeline. NT, K-major both operands
// stored as [rows, NSLAB*K], slab s at column offset s*K.
// D = sum over pairs (PA[p],PB[p]) of Aslab*Bslab^T.
// CTA tile 128x128, chunk BK=64. 8 warps: 2(m) x 4(n), each 64x32.
// EPI: 0 = fp32 store, 1 = tanh(acc+bias) fp32 store, 2 = split2 bf16 store
// ============================================================================
#define TILEB 16384  // bytes of one 128x64 bf16 SW128 tile

template<int NSLAB, int NPAIR, int EPI>
__global__ void __launch_bounds__(256) tgemm(
    const __nv_bfloat16* __restrict__ A, const __nv_bfloat16* __restrict__ B,
    float* __restrict__ Cf, __nv_bfloat16* __restrict__ Cs,
    const float* __restrict__ bias,
    int K, long long sA, long long sB, long long sC,
    int ldc, int splitOff)
{
    extern __shared__ char smem[];
    const uint32_t sb = smem_u32(smem);
    const int tid = threadIdx.x;
    const int lane = tid & 31, wid = tid >> 5;
    const int wm = wid & 1, wn = wid >> 1;         // warp tile: (wm*64, wn*32)
    const int n0 = blockIdx.x * 128, m0 = blockIdx.y * 128;
    const long long z = blockIdx.z;

    const __nv_bfloat16* Ab = A + z * sA;
    const __nv_bfloat16* Bb = B + z * sB;

    const int PA[6] = {0, 0, 1, 0, 2, 1};
    const int PB[6] = {0, 1, 0, 2, 0, 1};

    const int rowlen = NSLAB * K;
    const int nchunk = K >> 6;
    const uint32_t stageBytes = 2 * NSLAB * TILEB;

    float acc[4][4][4];
    #pragma unroll
    for (int i = 0; i < 4; i++)
        #pragma unroll
        for (int j = 0; j < 4; j++)
            #pragma unroll
            for (int q = 0; q < 4; q++) acc[i][j][q] = 0.f;

    // per-thread load coordinates (16B per thread per 1/4-tile)
    const int ldr = tid >> 3;            // row 0..31 base pattern via v
    (void)ldr;

    // ldmatrix lane-address components
    const int g = lane >> 3, lr = lane & 7;
    const int a_r  = lr + (g & 1) * 8;   // A: row add
    const int a_kb = (g >> 1) * 16;      // A: k-byte add
    const int b_r  = lr + (g >> 1) * 8;  // B: row add
    const int b_kb = (g & 1) * 16;       // B: k-byte add

    auto prefetch = [&](int c, int stage) {
        const int k0 = c << 6;
        const uint32_t sbase = sb + stage * stageBytes;
        #pragma unroll
        for (int s = 0; s < NSLAB; s++) {
            #pragma unroll
            for (int j = 0; j < 4; j++) {
                int v = tid + 256 * j;
                int r = v >> 3, cc = (v & 7) << 3;
                uint32_t off = (uint32_t)(r * 128 + cc * 2);
                off ^= (off >> 3) & 0x70u;
                CP_ASYNC16(sbase + s * TILEB + off,
                           Ab + (long long)(m0 + r) * rowlen + s * K + k0 + cc);
            }
            #pragma unroll
            for (int j = 0; j < 4; j++) {
                int v = tid + 256 * j;
                int r = v >> 3, cc = (v & 7) << 3;
                uint32_t off = (uint32_t)(r * 128 + cc * 2);
                off ^= (off >> 3) & 0x70u;
                CP_ASYNC16(sbase + (NSLAB + s) * TILEB + off,
                           Bb + (long long)(n0 + r) * rowlen + s * K + k0 + cc);
            }
        }
    };

    prefetch(0, 0);
    CP_COMMIT();

    for (int c = 0; c < nchunk; c++) {
        const int stage = c & 1;
        if (c + 1 < nchunk) {
            prefetch(c + 1, stage ^ 1);
            CP_COMMIT();
            CP_WAIT1();
        } else {
            CP_WAIT0();
        }
        __syncthreads();

        const uint32_t sbase = sb + stage * stageBytes;
        #pragma unroll
        for (int p = 0; p < NPAIR; p++) {
            const uint32_t aBase = sbase + PA[p] * TILEB;
            const uint32_t bBase = sbase + (NSLAB + PB[p]) * TILEB;
            #pragma unroll
            for (int kt = 0; kt < 4; kt++) {       // 4 k16 steps
                uint32_t afr[4][4], bfr[2][4];
                #pragma unroll
                for (int mt = 0; mt < 4; mt++) {
                    uint32_t off = (uint32_t)((wm * 64 + mt * 16 + a_r) * 128 + kt * 32 + a_kb);
                    off ^= (off >> 3) & 0x70u;
                    ldsm4(afr[mt], aBase + off);
                }
                #pragma unroll
                for (int ntp = 0; ntp < 2; ntp++) {
                    uint32_t off = (uint32_t)((wn * 32 + ntp * 16 + b_r) * 128 + kt * 32 + b_kb);
                    off ^= (off >> 3) & 0x70u;
                    ldsm4(bfr[ntp], bBase + off);
                }
                #pragma unroll
                for (int mt = 0; mt < 4; mt++)
                    #pragma unroll
                    for (int nt = 0; nt < 4; nt++)
                        mma_bf16(acc[mt][nt], afr[mt], &bfr[nt >> 1][(nt & 1) * 2]);
            }
        }
        __syncthreads();
    }

    // ---- epilogue (register accumulators) ----
    const int qr = lane >> 2;          // row within 8
    const int qc = (lane & 3) * 2;     // col pair
    #pragma unroll
    for (int mt = 0; mt < 4; mt++) {
        #pragma unroll
        for (int nt = 0; nt < 4; nt++) {
            const long long row0 = m0 + wm * 64 + mt * 16 + qr;
            const long long row1 = row0 + 8;
            const int col = n0 + wn * 32 + nt * 8 + qc;
            float v00 = acc[mt][nt][0], v01 = acc[mt][nt][1];
            float v10 = acc[mt][nt][2], v11 = acc[mt][nt][3];
            if (EPI == 0) {
                *reinterpret_cast<float2*>(Cf + z * sC + row0 * ldc + col) = make_float2(v00, v01);
                *reinterpret_cast<float2*>(Cf + z * sC + row1 * ldc + col) = make_float2(v10, v11);
            } else if (EPI == 1) {
                float b0 = bias[col], b1 = bias[col + 1];
                *reinterpret_cast<float2*>(Cf + z * sC + row0 * ldc + col) =
                    make_float2(tanhf(v00 + b0), tanhf(v01 + b1));
                *reinterpret_cast<float2*>(Cf + z * sC + row1 * ldc + col) =
                    make_float2(tanhf(v10 + b0), tanhf(v11 + b1));
            } else {
                __nv_bfloat16 h0, l0, h1, l1;
                split2f(v00, h0, l0); split2f(v01, h1, l1);
                *reinterpret_cast<__nv_bfloat162*>(Cs + z * sC + row0 * ldc + col) =
                    __nv_bfloat162(h0, h1);
                *reinterpret_cast<__nv_bfloat162*>(Cs + z * sC + row0 * ldc + splitOff + col) =
                    __nv_bfloat162(l0, l1);
                split2f(v10, h0, l0); split2f(v11, h1, l1);
                *reinterpret_cast<__nv_bfloat162*>(Cs + z * sC + row1 * ldc + col) =
                    __nv_bfloat162(h0, h1);
                *reinterpret_cast<__nv_bfloat162*>(Cs + z * sC + row1 * ldc + splitOff + col) =
                    __nv_bfloat162(l0, l1);
            }
        }
    }
}

// ============================================================================
// Conversion kernels
// ============================================================================
__global__ void __launch_bounds__(256) split3_kernel(
    const float* __restrict__ src, __nv_bfloat16* __restrict__ dst, int K)
{
    long long i = (long long)blockIdx.x * blockDim.x + threadIdx.x;
    long long rr = i / K;
    int k = (int)(i - rr * K);
    float x = src[i];
    __nv_bfloat16 h = __float2bfloat16(x);
    float rm = x - __bfloat162float(h);
    __nv_bfloat16 m = __float2bfloat16(rm);
    __nv_bfloat16 l = __float2bfloat16(rm - __bfloat162float(m));
    __nv_bfloat16* row = dst + rr * (3LL * K);
    row[k] = h; row[K + k] = m; row[2 * K + k] = l;
}

__global__ void __launch_bounds__(256) split2_kernel(
    const float* __restrict__ src, __nv_bfloat16* __restrict__ dst, int K)
{
    long long i = (long long)blockIdx.x * blockDim.x + threadIdx.x;
    long long rr = i / K;
    int k = (int)(i - rr * K);
    __nv_bfloat16 h, l;
    split2f(src[i], h, l);
    __nv_bfloat16* row = dst + rr * (2LL * K);
    row[k] = h; row[K + k] = l;
}

// dec -> cat region: cat [8192, 4096]: hi slab cols [0,2048), lo [2048,4096);
// dec occupies cat cols [1024,2048) -> hi at 1024+o, lo at 3072+o
__global__ void __launch_bounds__(256) dec_to_cat_kernel(
    const float* __restrict__ dec, __nv_bfloat16* __restrict__ cat)
{
    long long i = (long long)blockIdx.x * blockDim.x + threadIdx.x;  // over 8192*1024
    long long m = i >> 10;
    int o = (int)(i & 1023);
    __nv_bfloat16 h, l;
    split2f(dec[i], h, l);
    cat[m * 4096 + 1024 + o] = h;
    cat[m * 4096 + 3072 + o] = l;
}

// enc -> enc2 [b][s, 2048] and encT2 [b][i, 2048] (transposed), both h|l
__global__ void __launch_bounds__(1024) enc_split_kernel(
    const float* __restrict__ enc, __nv_bfloat16* __restrict__ e2, __nv_bfloat16* __restrict__ eT2)
{
    __shared__ __nv_bfloat16 sh[32][33], sl[32][33];
    int b = blockIdx.z;
    int i0 = blockIdx.x * 32, s0 = blockIdx.y * 32;
    int tx = threadIdx.x, ty = threadIdx.y;
    const float* eb = enc + (size_t)b * S_ * I_;
    float x = eb[(size_t)(s0 + ty) * I_ + i0 + tx];
    __nv_bfloat16 h, l;
    split2f(x, h, l);
    __nv_bfloat16* e2b = e2 + (size_t)b * S_ * 2 * I_;
    e2b[(size_t)(s0 + ty) * 2048 + i0 + tx] = h;
    e2b[(size_t)(s0 + ty) * 2048 + 1024 + i0 + tx] = l;
    sh[ty][tx] = h; sl[ty][tx] = l;
    __syncthreads();
    __nv_bfloat16* eTb = eT2 + (size_t)b * I_ * 2 * S_;
    eTb[(size_t)(i0 + ty) * 2048 + s0 + tx] = sh[tx][ty];
    eTb[(size_t)(i0 + ty) * 2048 + 1024 + s0 + tx] = sl[tx][ty];
}

// ============================================================================
// Masked softmax over rows of [B*T, S=1024], in place (fp32), + fused 2-way
// split to wsplit [row, 2048]. mask int32: !=0 -> weight 0.
// ============================================================================
__device__ __forceinline__ float warpMax(float v) {
    #pragma unroll
    for (int o = 16; o; o >>= 1) v = fmaxf(v, __shfl_xor_sync(0xffffffffu, v, o));
    return v;
}
__device__ __forceinline__ float warpSum(float v) {
    #pragma unroll
    for (int o = 16; o; o >>= 1) v += __shfl_xor_sync(0xffffffffu, v, o);
    return v;
}

__global__ void __launch_bounds__(256) softmax_mask(
    float* __restrict__ w, const int* __restrict__ mask, __nv_bfloat16* __restrict__ wsplit)
{
    const int S = 1024;
    long long row = blockIdx.x;
    int b = (int)(row >> 7);  // T = 128
    float* sr = w + row * S;
    const int* mr = mask + (long long)b * S;
    int tid = threadIdx.x;

    float4 v = *reinterpret_cast<const float4*>(sr + tid * 4);
    int4 m = *reinterpret_cast<const int4*>(mr + tid * 4);

    bool msk[4] = {m.x != 0, m.y != 0, m.z != 0, m.w != 0};
    float x[4];
    x[0] = msk[0] ? -INFINITY : v.x;
    x[1] = msk[1] ? -INFINITY : v.y;
    x[2] = msk[2] ? -INFINITY : v.z;
    x[3] = msk[3] ? -INFINITY : v.w;

    float mx = fmaxf(fmaxf(x[0], x[1]), fmaxf(x[2], x[3]));

    __shared__ float sh[8];
    float wm = warpMax(mx);
    if ((tid & 31) == 0) sh[tid >> 5] = wm;
    __syncthreads();
    if (tid < 32) {
        float t = (tid < 8) ? sh[tid] : -INFINITY;
        t = warpMax(t);
        if (tid == 0) sh[0] = t;
    }
    __syncthreads();
    mx = sh[0];

    float e[4], s = 0.f;
    #pragma unroll
    for (int j = 0; j < 4; j++) {
        e[j] = msk[j] ? 0.f : __expf(x[j] - mx);
        s += e[j];
    }
    __syncthreads();
    float ws = warpSum(s);
    if ((tid & 31) == 0) sh[tid >> 5] = ws;
    __syncthreads();
    if (tid < 32) {
        float t = (tid < 8) ? sh[tid] : 0.f;
        t = warpSum(t);
        if (tid == 0) sh[0] = t;
    }
    __syncthreads();
    float inv = 1.0f / sh[0];

    float o[4] = {e[0] * inv, e[1] * inv, e[2] * inv, e[3] * inv};
    float4 of = {o[0], o[1], o[2], o[3]};
    *reinterpret_cast<float4*>(sr + tid * 4) = of;

    __nv_bfloat16* wrow = wsplit + row * 2048;
    #pragma unroll
    for (int j = 0; j < 4; j++) {
        __nv_bfloat16 h, l;
        split2f(o[j], h, l);
        wrow[tid * 4 + j] = h;
        wrow[1024 + tid * 4 + j] = l;
    }
}

// ============================================================================
extern "C" void kernel_launch(void* const* d_in, const int* in_sizes, int n_in,
                              void* d_out, int out_size)
{
    const float* dec    = (const float*)d_in[0];   // [64,128,1024]
    const float* enc    = (const float*)d_in[1];   // [64,1024,1024]
    const int*   mask   = (const int*)d_in[2];     // [64,1024] bool->int32
    const float* W_attn = (const float*)d_in[3];   // [1024,1024]
    const float* W_out  = (const float*)d_in[4];   // [1024,2048]
    const float* b_out  = (const float*)d_in[5];   // [1024]

    float* out     = (float*)d_out;                 // attn_outputs [64,128,1024]
    float* weights = out + (long long)M_ * O_;      // attn_weights [64,128,1024]

    __nv_bfloat16 *dec3, *wa3, *qp2, *enc2, *encT2, *w2, *cat2, *wo2;
    cudaGetSymbolAddress((void**)&dec3,  g_dec3);
    cudaGetSymbolAddress((void**)&wa3,   g_wa3);
    cudaGetSymbolAddress((void**)&qp2,   g_qp2);
    cudaGetSymbolAddress((void**)&enc2,  g_enc2);
    cudaGetSymbolAddress((void**)&encT2, g_encT2);
    cudaGetSymbolAddress((void**)&w2,    g_w2);
    cudaGetSymbolAddress((void**)&cat2,  g_cat2);
    cudaGetSymbolAddress((void**)&wo2,   g_wo2);

    const int SM3 = 2 * 6 * TILEB;  // 196608 (2 stages x 6 tiles)
    const int SM2 = 2 * 4 * TILEB;  // 131072 (2 stages x 4 tiles)
    cudaFuncSetAttribute((const void*)tgemm<3, 6, 2>, cudaFuncAttributeMaxDynamicSharedMemorySize, SM3);
    cudaFuncSetAttribute((const void*)tgemm<2, 3, 0>, cudaFuncAttributeMaxDynamicSharedMemorySize, SM2);
    cudaFuncSetAttribute((const void*)tgemm<2, 3, 2>, cudaFuncAttributeMaxDynamicSharedMemorySize, SM2);
    cudaFuncSetAttribute((const void*)tgemm<2, 3, 1>, cudaFuncAttributeMaxDynamicSharedMemorySize, SM2);

    // --- Conversions ---
    split3_kernel<<<(M_ * (long long)O_) / 256, 256>>>(dec, dec3, O_);
    split3_kernel<<<(I_ * (long long)O_) / 256, 256>>>(W_attn, wa3, O_);
    enc_split_kernel<<<dim3(I_ / 32, S_ / 32, B_), dim3(32, 32)>>>(enc, enc2, encT2);
    split2_kernel<<<(O_ * (long long)C_) / 256, 256>>>(W_out, wo2, C_);
    dec_to_cat_kernel<<<(M_ * (long long)O_) / 256, 256>>>(dec, cat2);

    // --- GEMM1: q_proj = dec . W_attn^T  (3-way split, 6 passes) -> qp2 split ---
    tgemm<3, 6, 2><<<dim3(I_ / 128, M_ / 128, 1), 256, SM3>>>(
        dec3, wa3, nullptr, qp2, nullptr,
        O_, 0, 0, 0, 2 * I_, I_);

    // --- GEMM2: scores[b] = q[b] . enc[b]^T  (2-way split) -> weights fp32 ---
    tgemm<2, 3, 0><<<dim3(S_ / 128, T_ / 128, B_), 256, SM2>>>(
        qp2, enc2, weights, nullptr, nullptr,
        I_, (long long)T_ * 2 * I_, (long long)S_ * 2 * I_, (long long)T_ * S_,
        S_, 0);

    // --- Softmax + fused split -> w2 ---
    softmax_mask<<<M_, 256>>>(weights, mask, w2);

    // --- GEMM4: ctx[b] = w[b] . encT[b]^T -> cat2 split (ctx cols [0,1024)) ---
    tgemm<2, 3, 2><<<dim3(I_ / 128, T_ / 128, B_), 256, SM2>>>(
        w2, encT2, nullptr, cat2, nullptr,
        S_, (long long)T_ * 2 * S_, (long long)I_ * 2 * S_, (long long)T_ * 2 * C_,
        2 * C_, C_);

    // --- GEMM5: out = tanh(cat . W_out^T + b) ---
    tgemm<2, 3, 1><<<dim3(O_ / 128, M_ / 128, 1), 256, SM2>>>(
        cat2, wo2, out, nullptr, b_out,
        C_, 0, 0, 0, O_, 0);
}